// round 7
// baseline (speedup 1.0000x reference)
#include <cuda_runtime.h>
#include <cuda_bf16.h>
#include <cstdint>

#define BATCH 8
#define CH    512
#define NSP   4096
#define HOFF  ((size_t)BATCH * CH * CH)

// packed row layout: [k/32 chunk][hi 32 | lo 32] bf16  (64 elems = 128B per chunk)
__device__ __align__(16) __nv_bfloat16 g_w   [(size_t)3 * CH * (CH * 2)];
__device__ __align__(16) __nv_bfloat16 g_xt  [(size_t)BATCH * NSP * (CH * 2)];
__device__ __align__(16) __nv_bfloat16 g_q   [(size_t)BATCH * CH * (NSP * 2)];
__device__ __align__(16) __nv_bfloat16 g_k   [(size_t)BATCH * CH * (NSP * 2)];
__device__ __align__(16) __nv_bfloat16 g_vt  [(size_t)BATCH * NSP * (CH * 2)];
__device__ __align__(16) __nv_bfloat16 g_attn_p[(size_t)BATCH * CH * (CH * 2)];
__device__ __align__(16) float         g_attn_raw[(size_t)2 * BATCH * CH * CH];

// ---------------- low-level helpers ----------------
__device__ __forceinline__ uint32_t smem_u32(const void* p) {
    uint32_t a;
    asm("{ .reg .u64 t; cvta.to.shared.u64 t, %1; cvt.u32.u64 %0, t; }" : "=r"(a) : "l"(p));
    return a;
}
__device__ __forceinline__ void cp16(uint32_t s, const void* g) {
    asm volatile("cp.async.cg.shared.global [%0], [%1], 16;" :: "r"(s), "l"(g));
}
__device__ __forceinline__ void ldsm4(uint32_t* r, uint32_t addr) {
    asm volatile("ldmatrix.sync.aligned.m8n8.x4.shared.b16 {%0,%1,%2,%3}, [%4];"
                 : "=r"(r[0]), "=r"(r[1]), "=r"(r[2]), "=r"(r[3]) : "r"(addr));
}
__device__ __forceinline__ void mma16816(float* d, const uint32_t* a, const uint32_t* b) {
    asm volatile("mma.sync.aligned.m16n8k16.row.col.f32.bf16.bf16.f32 "
                 "{%0,%1,%2,%3}, {%4,%5,%6,%7}, {%8,%9}, {%0,%1,%2,%3};"
                 : "+f"(d[0]), "+f"(d[1]), "+f"(d[2]), "+f"(d[3])
                 : "r"(a[0]), "r"(a[1]), "r"(a[2]), "r"(a[3]), "r"(b[0]), "r"(b[1]));
}
__device__ __forceinline__ void split2(float f, __nv_bfloat16& h, __nv_bfloat16& l) {
    h = __float2bfloat16(f);
    l = __float2bfloat16(f - __bfloat162float(h));
}
__device__ __forceinline__ uint32_t packbf(float a, float b) {
    __nv_bfloat16 ha = __float2bfloat16(a), hb = __float2bfloat16(b);
    return (uint32_t)__bfloat16_as_ushort(ha) | ((uint32_t)__bfloat16_as_ushort(hb) << 16);
}
__device__ __forceinline__ uint32_t packbf_lo(float a, float b) {
    __nv_bfloat16 ha = __float2bfloat16(a), hb = __float2bfloat16(b);
    float ra = a - __bfloat162float(ha), rb = b - __bfloat162float(hb);
    __nv_bfloat16 la = __float2bfloat16(ra), lb = __float2bfloat16(rb);
    return (uint32_t)__bfloat16_as_ushort(la) | ((uint32_t)__bfloat16_as_ushort(lb) << 16);
}
// packed column offset for logical k within a row
#define PCK(k) ((((k) >> 5) << 6) + ((k) & 31))

// load one 128-row x 128B chunk tile (16KB) into smem, XOR-8 swizzle on 16B units
__device__ __forceinline__ void load_tile(uint32_t sdst, const __nv_bfloat16* gsrc,
                                          size_t rowlen, int tid) {
    #pragma unroll
    for (int i = 0; i < 4; i++) {
        int idx = tid + i * 256;
        int r = idx >> 3, u = idx & 7;
        cp16(sdst + r * 128 + ((u ^ (r & 7)) << 4),
             gsrc + (size_t)r * rowlen + u * 8);
    }
}

// ---------------- GEMM core: acc[2][8][4] += A[128,K] * B[128,K]^T ----------------
// 8 warps: warp tile 32x64, wm=(w>>1)*32, wn=(w&1)*64. 3-stage cp.async pipeline.
__device__ __forceinline__ void gemm_core(const __nv_bfloat16* __restrict__ Ag,
                                          const __nv_bfloat16* __restrict__ Bg,
                                          int nch, size_t lda, size_t ldb,
                                          float (&acc)[2][8][4]) {
    extern __shared__ char smem[];
    const uint32_t sb = smem_u32(smem);
    const int tid = threadIdx.x;
    const int lane = tid & 31, w = tid >> 5;
    const int wm = (w >> 1) * 32, wn = (w & 1) * 64;

    #pragma unroll
    for (int i = 0; i < 2; i++)
        #pragma unroll
        for (int j = 0; j < 8; j++)
            #pragma unroll
            for (int r = 0; r < 4; r++) acc[i][j][r] = 0.f;

    // stages: s*32768 = A(16KB) | B(16KB)
    load_tile(sb,         Ag, lda, tid);
    load_tile(sb + 16384, Bg, ldb, tid);
    asm volatile("cp.async.commit_group;" ::: "memory");
    load_tile(sb + 32768, Ag + 64, lda, tid);
    load_tile(sb + 49152, Bg + 64, ldb, tid);
    asm volatile("cp.async.commit_group;" ::: "memory");

    for (int ch = 0; ch < nch; ch++) {
        asm volatile("cp.async.wait_group 1;" ::: "memory");
        __syncthreads();
        if (ch + 2 < nch) {
            const uint32_t st = sb + ((ch + 2) % 3) * 32768;
            load_tile(st,         Ag + (size_t)(ch + 2) * 64, lda, tid);
            load_tile(st + 16384, Bg + (size_t)(ch + 2) * 64, ldb, tid);
        }
        asm volatile("cp.async.commit_group;" ::: "memory");

        const uint32_t s_a = sb + (ch % 3) * 32768;
        const uint32_t s_b = s_a + 16384;
        #pragma unroll
        for (int ks = 0; ks < 2; ks++) {
            uint32_t ah[2][4], al[2][4], bh[4][4], bl[4][4];
            #pragma unroll
            for (int i = 0; i < 2; i++) {
                int r = wm + 16 * i + (lane & 7) + ((lane >> 3) & 1) * 8;
                int u = 2 * ks + ((lane >> 4) & 1);
                ldsm4(ah[i], s_a + r * 128 + (((u    ) ^ (r & 7)) << 4));
                ldsm4(al[i], s_a + r * 128 + (((u + 4) ^ (r & 7)) << 4));
            }
            #pragma unroll
            for (int jj = 0; jj < 4; jj++) {
                int r = wn + 16 * jj + (lane & 7) + ((lane >> 4) & 1) * 8;
                int u = 2 * ks + ((lane >> 3) & 1);
                ldsm4(bh[jj], s_b + r * 128 + (((u    ) ^ (r & 7)) << 4));
                ldsm4(bl[jj], s_b + r * 128 + (((u + 4) ^ (r & 7)) << 4));
            }
            #pragma unroll
            for (int i = 0; i < 2; i++)
                #pragma unroll
                for (int j = 0; j < 8; j++)
                    mma16816(acc[i][j], ah[i], &bh[j >> 1][(j & 1) * 2]);
            #pragma unroll
            for (int i = 0; i < 2; i++)
                #pragma unroll
                for (int j = 0; j < 8; j++)
                    mma16816(acc[i][j], al[i], &bh[j >> 1][(j & 1) * 2]);
            #pragma unroll
            for (int i = 0; i < 2; i++)
                #pragma unroll
                for (int j = 0; j < 8; j++)
                    mma16816(acc[i][j], ah[i], &bl[j >> 1][(j & 1) * 2]);
        }
    }
    asm volatile("cp.async.wait_group 0;" ::: "memory");
    __syncthreads();
}

// ---------------- kernel 1: QKV projections ----------------
// grid (NSP/128=32, CH/128=4, BATCH*3)
__global__ __launch_bounds__(256, 2) void qkv_gemm(
    const float* __restrict__ bq, const float* __restrict__ bk, const float* __restrict__ bv)
{
    const int z = blockIdx.z;
    const int batch = z / 3, which = z % 3;
    const int c0 = blockIdx.y * 128, n0 = blockIdx.x * 128;

    const __nv_bfloat16* Ag = g_w + (size_t)which * CH * (CH * 2) + (size_t)c0 * (CH * 2);
    const __nv_bfloat16* Bg = g_xt + ((size_t)batch * NSP + n0) * (CH * 2);

    float acc[2][8][4];
    gemm_core(Ag, Bg, CH / 32, CH * 2, CH * 2, acc);

    const float* bias = (which == 0) ? bq : (which == 1) ? bk : bv;
    const int tid = threadIdx.x, lane = tid & 31, w = tid >> 5;
    const int wm = (w >> 1) * 32, wn = (w & 1) * 64;

    if (which < 2) {
        // direct packed store, rows = c, K = n
        __nv_bfloat16* base = ((which == 0) ? g_q : g_k) + ((size_t)batch * CH) * (NSP * 2);
        #pragma unroll
        for (int i = 0; i < 2; i++)
            #pragma unroll
            for (int r2 = 0; r2 < 2; r2++) {
                int m = wm + 16 * i + (lane >> 2) + 8 * r2;
                float bvv = bias[c0 + m];
                __nv_bfloat16* dst = base + (size_t)(c0 + m) * (NSP * 2);
                #pragma unroll
                for (int j = 0; j < 8; j++) {
                    int n = n0 + wn + 8 * j + 2 * (lane & 3);
                    float f0 = acc[i][j][2 * r2] + bvv;
                    float f1 = acc[i][j][2 * r2 + 1] + bvv;
                    int off = PCK(n);
                    *(uint32_t*)(dst + off)      = packbf(f0, f1);
                    *(uint32_t*)(dst + off + 32) = packbf_lo(f0, f1);
                }
            }
    } else {
        // v: transpose through smem, store vt rows = n, K = c
        extern __shared__ char smem[];
        float* smemf = (float*)smem;                 // 128 x 132 floats = 67.6KB
        #pragma unroll
        for (int i = 0; i < 2; i++)
            #pragma unroll
            for (int j = 0; j < 8; j++)
                #pragma unroll
                for (int r = 0; r < 4; r++) {
                    int m  = wm + 16 * i + (lane >> 2) + 8 * (r >> 1);
                    int nl = wn + 8 * j + 2 * (lane & 3) + (r & 1);
                    smemf[nl * 132 + m] = acc[i][j][r] + bias[c0 + m];
                }
        __syncthreads();
        #pragma unroll 4
        for (int rr = 0; rr < 16; rr++) {
            int nl = w * 16 + rr;
            const float* src = smemf + nl * 132 + 4 * lane;
            float4 v4 = make_float4(src[0], src[1], src[2], src[3]);
            int c = c0 + 4 * lane;
            __nv_bfloat16* dst = g_vt + ((size_t)batch * NSP + n0 + nl) * (CH * 2);
            int off = PCK(c);
            uint32_t h0 = packbf(v4.x, v4.y),    h1 = packbf(v4.z, v4.w);
            uint32_t l0 = packbf_lo(v4.x, v4.y), l1 = packbf_lo(v4.z, v4.w);
            *(uint2*)(dst + off)      = make_uint2(h0, h1);
            *(uint2*)(dst + off + 32) = make_uint2(l0, l1);
        }
    }
}

// ---------------- kernel 2: attn = q @ k^T (split-K by 2) ----------------
// grid (CH/128=4, CH/128=4, BATCH*2); z = batch*2 + khalf
__global__ __launch_bounds__(256, 2) void attn_gemm()
{
    const int z = blockIdx.z;
    const int batch = z >> 1, khalf = z & 1;
    const int c0 = blockIdx.y * 128, d0 = blockIdx.x * 128;

    const __nv_bfloat16* Ag = g_q + ((size_t)batch * CH + c0) * (NSP * 2) + (size_t)khalf * NSP;
    const __nv_bfloat16* Bg = g_k + ((size_t)batch * CH + d0) * (NSP * 2) + (size_t)khalf * NSP;

    float acc[2][8][4];
    gemm_core(Ag, Bg, (NSP / 2) / 32, NSP * 2, NSP * 2, acc);

    const int tid = threadIdx.x, lane = tid & 31, w = tid >> 5;
    const int wm = (w >> 1) * 32, wn = (w & 1) * 64;
    float* base = g_attn_raw + (size_t)khalf * HOFF + ((size_t)batch * CH) * CH;

    #pragma unroll
    for (int i = 0; i < 2; i++)
        #pragma unroll
        for (int r2 = 0; r2 < 2; r2++) {
            int m = wm + 16 * i + (lane >> 2) + 8 * r2;
            float* dst = base + (size_t)(c0 + m) * CH + d0;
            #pragma unroll
            for (int j = 0; j < 8; j++) {
                int nl = wn + 8 * j + 2 * (lane & 3);
                *(float2*)(dst + nl) = make_float2(acc[i][j][2 * r2], acc[i][j][2 * r2 + 1]);
            }
        }
}

// ---------------- kernel 3: softmax (sums split-K halves) + hi/lo pack ----------------
__global__ __launch_bounds__(256) void softmax_kernel()
{
    const size_t row = blockIdx.x;
    const float* p = g_attn_raw + row * CH;
    const int tid = threadIdx.x;

    float v0 = p[tid] + p[HOFF + tid];
    float v1 = p[tid + 256] + p[HOFF + tid + 256];

    __shared__ float red[8];
    float m = fmaxf(v0, v1);
    #pragma unroll
    for (int o = 16; o > 0; o >>= 1) m = fmaxf(m, __shfl_xor_sync(0xffffffffu, m, o));
    if ((tid & 31) == 0) red[tid >> 5] = m;
    __syncthreads();
    if (tid < 8) {
        float t = red[tid];
        #pragma unroll
        for (int o = 4; o > 0; o >>= 1) t = fmaxf(t, __shfl_xor_sync(0xffu, t, o));
        red[tid] = t;
    }
    __syncthreads();
    m = red[0];

    float e0 = expf(v0 - m), e1 = expf(v1 - m);

    __shared__ float red2[8];
    float s = e0 + e1;
    #pragma unroll
    for (int o = 16; o > 0; o >>= 1) s += __shfl_xor_sync(0xffffffffu, s, o);
    if ((tid & 31) == 0) red2[tid >> 5] = s;
    __syncthreads();
    if (tid < 8) {
        float t = red2[tid];
        #pragma unroll
        for (int o = 4; o > 0; o >>= 1) t += __shfl_xor_sync(0xffu, t, o);
        red2[tid] = t;
    }
    __syncthreads();
    s = red2[0];

    const float inv = 1.0f / s;
    __nv_bfloat16 h, l;
    __nv_bfloat16* dst = g_attn_p + row * (CH * 2);
    split2(e0 * inv, h, l);
    dst[PCK(tid)]      = h;
    dst[PCK(tid) + 32] = l;
    split2(e1 * inv, h, l);
    dst[PCK(tid + 256)]      = h;
    dst[PCK(tid + 256) + 32] = l;
}

// ---------------- kernel 4: out = attn @ v + x ----------------
// grid (NSP/128=32, CH/128=4, BATCH)
__global__ __launch_bounds__(256, 2) void out_gemm(
    const float* __restrict__ x, float* __restrict__ out)
{
    const int batch = blockIdx.z;
    const int c0 = blockIdx.y * 128, n0 = blockIdx.x * 128;

    const __nv_bfloat16* Ag = g_attn_p + ((size_t)batch * CH + c0) * (CH * 2);
    const __nv_bfloat16* Bg = g_vt + ((size_t)batch * NSP + n0) * (CH * 2);

    float acc[2][8][4];
    gemm_core(Ag, Bg, CH / 32, CH * 2, CH * 2, acc);

    const int tid = threadIdx.x, lane = tid & 31, w = tid >> 5;
    const int wm = (w >> 1) * 32, wn = (w & 1) * 64;

    #pragma unroll
    for (int i = 0; i < 2; i++)
        #pragma unroll
        for (int r2 = 0; r2 < 2; r2++) {
            int m = wm + 16 * i + (lane >> 2) + 8 * r2;
            size_t rowoff = ((size_t)batch * CH + c0 + m) * NSP + n0;
            #pragma unroll
            for (int j = 0; j < 8; j++) {
                int nl = wn + 8 * j + 2 * (lane & 3);
                float2 xv = *(const float2*)(x + rowoff + nl);
                *(float2*)(out + rowoff + nl) = make_float2(
                    acc[i][j][2 * r2] + xv.x, acc[i][j][2 * r2 + 1] + xv.y);
            }
        }
}

// ---------------- split / pack kernels ----------------
__global__ __launch_bounds__(256) void split_w_kernel(
    const float* __restrict__ wq, const float* __restrict__ wk, const float* __restrict__ wv)
{
    int idx = blockIdx.x * 256 + threadIdx.x;
    int which = idx >> 18;
    int rem = idx & 0x3FFFF;
    int row = rem >> 9, kk = rem & 511;
    const float* wsrc = (which == 0) ? wq : (which == 1) ? wk : wv;
    float f = wsrc[row * CH + kk];
    __nv_bfloat16 h, l; split2(f, h, l);
    __nv_bfloat16* dst = g_w + (size_t)which * CH * (CH * 2) + (size_t)row * (CH * 2) + PCK(kk);
    dst[0] = h; dst[32] = l;
}

// x[b][c][n] -> xt packed rows n, K = c
__global__ __launch_bounds__(256) void split_xt_kernel(const float* __restrict__ x)
{
    __shared__ float t[32][33];
    const int b = blockIdx.z;
    const int n0 = blockIdx.x * 32, c0 = blockIdx.y * 32;
    const int tx = threadIdx.x, ty = threadIdx.y;      // 32 x 8
    #pragma unroll
    for (int i = 0; i < 4; i++) {
        int c = c0 + ty + i * 8;
        t[ty + i * 8][tx] = x[((size_t)b * CH + c) * NSP + n0 + tx];
    }
    __syncthreads();
    #pragma unroll
    for (int i = 0; i < 4; i++) {
        int nl = ty + i * 8;
        float f = t[tx][nl];
        __nv_bfloat16 h, l; split2(f, h, l);
        int c = c0 + tx;
        __nv_bfloat16* dst = g_xt + ((size_t)b * NSP + n0 + nl) * (CH * 2) + PCK(c);
        dst[0] = h; dst[32] = l;
    }
}

// ---------------- launch ----------------
extern "C" void kernel_launch(void* const* d_in, const int* in_sizes, int n_in,
                              void* d_out, int out_size) {
    const float* x  = (const float*)d_in[0];
    const float* wq = (const float*)d_in[1];
    const float* bq = (const float*)d_in[2];
    const float* wk = (const float*)d_in[3];
    const float* bk = (const float*)d_in[4];
    const float* wv = (const float*)d_in[5];
    const float* bv = (const float*)d_in[6];
    float* out = (float*)d_out;

    const int SMEM = 98304;   // 3 stages x 32KB; >= 67.6KB v-epilogue staging
    cudaFuncSetAttribute(qkv_gemm,  cudaFuncAttributeMaxDynamicSharedMemorySize, SMEM);
    cudaFuncSetAttribute(attn_gemm, cudaFuncAttributeMaxDynamicSharedMemorySize, SMEM);
    cudaFuncSetAttribute(out_gemm,  cudaFuncAttributeMaxDynamicSharedMemorySize, SMEM);

    split_w_kernel<<<3 * CH * CH / 256, 256>>>(wq, wk, wv);
    split_xt_kernel<<<dim3(NSP / 32, CH / 32, BATCH), dim3(32, 8)>>>(x);

    qkv_gemm<<<dim3(NSP / 128, CH / 128, BATCH * 3), 256, SMEM>>>(bq, bk, bv);

    attn_gemm<<<dim3(CH / 128, CH / 128, BATCH * 2), 256, SMEM>>>();

    softmax_kernel<<<BATCH * CH, 256>>>();

    out_gemm<<<dim3(NSP / 128, CH / 128, BATCH), 256, SMEM>>>(x, out);
}

// round 8
// speedup vs baseline: 1.4124x; 1.4124x over previous
#include <cuda_runtime.h>
#include <cuda_bf16.h>
#include <cstdint>

#define BATCH 8
#define CH    512
#define NSP   4096

// ---------------- global scratch, all hi/lo K-packed ----------------
// packed row layout: [k/64 chunk][hi 64 | lo 64] bf16  (128 elems = 256B per chunk)
__device__ __align__(16) __nv_bfloat16 g_w   [(size_t)3 * CH * (CH * 2)];
__device__ __align__(16) __nv_bfloat16 g_xt  [(size_t)BATCH * NSP * (CH * 2)];
__device__ __align__(16) __nv_bfloat16 g_q   [(size_t)BATCH * CH * (NSP * 2)];
__device__ __align__(16) __nv_bfloat16 g_k   [(size_t)BATCH * CH * (NSP * 2)];
__device__ __align__(16) __nv_bfloat16 g_vt  [(size_t)BATCH * NSP * (CH * 2)];
__device__ __align__(16) __nv_bfloat16 g_attn_p[(size_t)BATCH * CH * (CH * 2)];
__device__ __align__(16) float         g_attn_raw[(size_t)BATCH * CH * CH];

// ---------------- low-level helpers ----------------
__device__ __forceinline__ uint32_t smem_u32(const void* p) {
    uint32_t a;
    asm("{ .reg .u64 t; cvta.to.shared.u64 t, %1; cvt.u32.u64 %0, t; }" : "=r"(a) : "l"(p));
    return a;
}
__device__ __forceinline__ void cp16(uint32_t s, const void* g) {
    asm volatile("cp.async.cg.shared.global [%0], [%1], 16;" :: "r"(s), "l"(g));
}
__device__ __forceinline__ void ldsm4(uint32_t* r, uint32_t addr) {
    asm volatile("ldmatrix.sync.aligned.m8n8.x4.shared.b16 {%0,%1,%2,%3}, [%4];"
                 : "=r"(r[0]), "=r"(r[1]), "=r"(r[2]), "=r"(r[3]) : "r"(addr));
}
__device__ __forceinline__ void mma16816(float* d, const uint32_t* a, const uint32_t* b) {
    asm volatile("mma.sync.aligned.m16n8k16.row.col.f32.bf16.bf16.f32 "
                 "{%0,%1,%2,%3}, {%4,%5,%6,%7}, {%8,%9}, {%0,%1,%2,%3};"
                 : "+f"(d[0]), "+f"(d[1]), "+f"(d[2]), "+f"(d[3])
                 : "r"(a[0]), "r"(a[1]), "r"(a[2]), "r"(a[3]), "r"(b[0]), "r"(b[1]));
}
__device__ __forceinline__ void split2(float f, __nv_bfloat16& h, __nv_bfloat16& l) {
    h = __float2bfloat16(f);
    l = __float2bfloat16(f - __bfloat162float(h));
}

// Load one 128-row x 256B chunk tile into smem with XOR-8 swizzle on 16B units.
__device__ __forceinline__ void load_tile(uint32_t sdst, const __nv_bfloat16* gsrc,
                                          size_t rowlen, int tid) {
    #pragma unroll
    for (int i = 0; i < 8; i++) {
        int idx = tid + i * 256;
        int r = idx >> 4, u = idx & 15;
        cp16(sdst + r * 256 + ((u ^ (r & 7)) * 16),
             gsrc + (size_t)r * rowlen + u * 8);
    }
}

// ---------------- GEMM core: C[128][128] += A[128,K] * B[128,K]^T ----------------
// A,B rows K-major hi/lo packed (chunk = 64 elems = hi64|lo64 = 256B). nch = K/64.
// 3-stage cp.async pipeline, prefetch issued BEFORE compute each iteration.
template<int TERMS>
__device__ __forceinline__ void gemm_core(const __nv_bfloat16* __restrict__ Ag,
                                          const __nv_bfloat16* __restrict__ Bg,
                                          int nch, size_t lda, size_t ldb,
                                          float (&acc)[4][4][4]) {
    extern __shared__ char smem[];
    const uint32_t sb = smem_u32(smem);
    const int tid = threadIdx.x;
    const int lane = tid & 31, w = tid >> 5;
    const int wm = (w >> 2) * 64, wn = (w & 3) * 32;

    #pragma unroll
    for (int i = 0; i < 4; i++)
        #pragma unroll
        for (int j = 0; j < 4; j++)
            #pragma unroll
            for (int r = 0; r < 4; r++) acc[i][j][r] = 0.f;

    // stages: s*65536 = A(32KB) | B(32KB)
    load_tile(sb,         Ag, lda, tid);
    load_tile(sb + 32768, Bg, ldb, tid);
    asm volatile("cp.async.commit_group;" ::: "memory");
    if (nch > 1) {
        load_tile(sb + 65536, Ag + 128, lda, tid);
        load_tile(sb + 98304, Bg + 128, ldb, tid);
    }
    asm volatile("cp.async.commit_group;" ::: "memory");

    for (int ch = 0; ch < nch; ch++) {
        asm volatile("cp.async.wait_group 1;" ::: "memory");
        __syncthreads();
        // prefetch ch+2 into stage (ch+2)%3 = (ch-1)%3 (consumed before last sync)
        if (ch + 2 < nch) {
            const uint32_t st = sb + ((ch + 2) % 3) * 65536;
            load_tile(st,         Ag + (size_t)(ch + 2) * 128, lda, tid);
            load_tile(st + 32768, Bg + (size_t)(ch + 2) * 128, ldb, tid);
        }
        asm volatile("cp.async.commit_group;" ::: "memory");

        const uint32_t s_a = sb + (ch % 3) * 65536;
        const uint32_t s_b = s_a + 32768;
        #pragma unroll
        for (int ks = 0; ks < 4; ks++) {
            uint32_t ah[4][4], al[4][4], bh[2][4], bl[2][4];
            #pragma unroll
            for (int i = 0; i < 4; i++) {
                int r = wm + 16 * i + (lane & 7) + ((lane >> 3) & 1) * 8;
                int u = 2 * ks + ((lane >> 4) & 1);
                ldsm4(ah[i], s_a + r * 256 + ((u       ^ (r & 7)) * 16));
                ldsm4(al[i], s_a + r * 256 + (((u + 8) ^ (r & 7)) * 16));
            }
            #pragma unroll
            for (int jj = 0; jj < 2; jj++) {
                int r = wn + 16 * jj + (lane & 7) + ((lane >> 4) & 1) * 8;
                int u = 2 * ks + ((lane >> 3) & 1);
                ldsm4(bh[jj], s_b + r * 256 + ((u       ^ (r & 7)) * 16));
                ldsm4(bl[jj], s_b + r * 256 + (((u + 8) ^ (r & 7)) * 16));
            }
            #pragma unroll
            for (int i = 0; i < 4; i++)
                #pragma unroll
                for (int j = 0; j < 4; j++)
                    mma16816(acc[i][j], ah[i], &bh[j >> 1][(j & 1) * 2]);
            #pragma unroll
            for (int i = 0; i < 4; i++)
                #pragma unroll
                for (int j = 0; j < 4; j++)
                    mma16816(acc[i][j], ah[i], &bl[j >> 1][(j & 1) * 2]);
            #pragma unroll
            for (int i = 0; i < 4; i++)
                #pragma unroll
                for (int j = 0; j < 4; j++)
                    mma16816(acc[i][j], al[i], &bh[j >> 1][(j & 1) * 2]);
            if (TERMS == 4) {
                #pragma unroll
                for (int i = 0; i < 4; i++)
                    #pragma unroll
                    for (int j = 0; j < 4; j++)
                        mma16816(acc[i][j], al[i], &bl[j >> 1][(j & 1) * 2]);
            }
        }
        // no trailing sync needed: next iteration's wait+sync protects stage reuse
    }
    asm volatile("cp.async.wait_group 0;" ::: "memory");
    __syncthreads();
}

#define PITCH 132
__device__ __forceinline__ void store_acc(float* smemf, const float (&acc)[4][4][4],
                                          int lane, int wm, int wn, bool transpose) {
    #pragma unroll
    for (int i = 0; i < 4; i++)
        #pragma unroll
        for (int j = 0; j < 4; j++)
            #pragma unroll
            for (int r = 0; r < 4; r++) {
                int m = wm + 16 * i + (lane >> 2) + 8 * (r >> 1);
                int n = wn + 8 * j + 2 * (lane & 3) + (r & 1);
                if (transpose) smemf[n * PITCH + m] = acc[i][j][r];
                else           smemf[m * PITCH + n] = acc[i][j][r];
            }
}

// ---------------- kernel 1: QKV projections ----------------
// grid (NSP/128=32, CH/128=4, BATCH*3)
__global__ __launch_bounds__(256, 1) void qkv_gemm(
    const float* __restrict__ bq, const float* __restrict__ bk, const float* __restrict__ bv)
{
    const int z = blockIdx.z;
    const int batch = z / 3, which = z % 3;
    const int c0 = blockIdx.y * 128, n0 = blockIdx.x * 128;

    const __nv_bfloat16* Ag = g_w + (size_t)which * CH * (CH * 2) + (size_t)c0 * (CH * 2);
    const __nv_bfloat16* Bg = g_xt + ((size_t)batch * NSP + n0) * (CH * 2);

    float acc[4][4][4];
    gemm_core<3>(Ag, Bg, CH / 64, CH * 2, CH * 2, acc);

    extern __shared__ char smem[];
    float* smemf = (float*)smem;
    const int tid = threadIdx.x, lane = tid & 31, w = tid >> 5;
    const int wm = (w >> 2) * 64, wn = (w & 3) * 32;

    store_acc(smemf, acc, lane, wm, wn, which == 2);   // v stored transposed (rows=n)
    __syncthreads();

    const float* bias = (which == 0) ? bq : (which == 1) ? bk : bv;
    const int chunk = lane >> 4, part = (lane >> 3) & 1, sub = lane & 7;

    if (which < 2) {
        __nv_bfloat16* dst = ((which == 0) ? g_q : g_k)
                             + ((size_t)batch * CH + c0) * (NSP * 2) + (size_t)n0 * 2;
        #pragma unroll 4
        for (int rr = 0; rr < 16; rr++) {
            int row = w * 16 + rr;
            float bvv = bias[c0 + row];
            const float* src = smemf + row * PITCH + chunk * 64 + sub * 8;
            float4 f0 = *(const float4*)src, f1 = *(const float4*)(src + 4);
            float vv[8] = {f0.x + bvv, f0.y + bvv, f0.z + bvv, f0.w + bvv,
                           f1.x + bvv, f1.y + bvv, f1.z + bvv, f1.w + bvv};
            unsigned short o8[8];
            #pragma unroll
            for (int e = 0; e < 8; e++) {
                __nv_bfloat16 h = __float2bfloat16(vv[e]);
                if (part) h = __float2bfloat16(vv[e] - __bfloat162float(h));
                o8[e] = __bfloat16_as_ushort(h);
            }
            *(uint4*)(dst + (size_t)row * (NSP * 2) + chunk * 128 + part * 64 + sub * 8)
                = *(const uint4*)o8;
        }
    } else {
        __nv_bfloat16* dst = g_vt + ((size_t)batch * NSP + n0) * (CH * 2) + (size_t)c0 * 2;
        #pragma unroll 4
        for (int rr = 0; rr < 16; rr++) {
            int row = w * 16 + rr;                         // local n
            const float* src = smemf + row * PITCH + chunk * 64 + sub * 8;
            const float* bp  = bias + c0 + chunk * 64 + sub * 8;
            float4 f0 = *(const float4*)src, f1 = *(const float4*)(src + 4);
            float4 b0 = *(const float4*)bp,  b1 = *(const float4*)(bp + 4);
            float vv[8] = {f0.x + b0.x, f0.y + b0.y, f0.z + b0.z, f0.w + b0.w,
                           f1.x + b1.x, f1.y + b1.y, f1.z + b1.z, f1.w + b1.w};
            unsigned short o8[8];
            #pragma unroll
            for (int e = 0; e < 8; e++) {
                __nv_bfloat16 h = __float2bfloat16(vv[e]);
                if (part) h = __float2bfloat16(vv[e] - __bfloat162float(h));
                o8[e] = __bfloat16_as_ushort(h);
            }
            *(uint4*)(dst + (size_t)row * (CH * 2) + chunk * 128 + part * 64 + sub * 8)
                = *(const uint4*)o8;
        }
    }
}

// ---------------- kernel 2: attn = q @ k^T (3-term; ll dropped) ----------------
// grid (CH/128=4, CH/128=4, BATCH)
__global__ __launch_bounds__(256, 1) void attn_gemm()
{
    const int batch = blockIdx.z;
    const int c0 = blockIdx.y * 128, d0 = blockIdx.x * 128;

    const __nv_bfloat16* Ag = g_q + ((size_t)batch * CH + c0) * (NSP * 2);
    const __nv_bfloat16* Bg = g_k + ((size_t)batch * CH + d0) * (NSP * 2);

    float acc[4][4][4];
    gemm_core<3>(Ag, Bg, NSP / 64, NSP * 2, NSP * 2, acc);

    extern __shared__ char smem[];
    float* smemf = (float*)smem;
    const int tid = threadIdx.x, lane = tid & 31, w = tid >> 5;
    store_acc(smemf, acc, lane, (w >> 2) * 64, (w & 3) * 32, false);
    __syncthreads();

    #pragma unroll 4
    for (int rr = 0; rr < 16; rr++) {
        int row = w * 16 + rr;
        const float* src = smemf + row * PITCH + 4 * lane;
        *(float4*)(g_attn_raw + ((size_t)batch * CH + c0 + row) * CH + d0 + 4 * lane)
            = *(const float4*)src;
    }
}

// ---------------- kernel 3: softmax + hi/lo pack ----------------
__global__ __launch_bounds__(256) void softmax_kernel()
{
    const size_t row = blockIdx.x;
    const float* p = g_attn_raw + row * CH;
    const int tid = threadIdx.x;

    float v0 = p[tid], v1 = p[tid + 256];

    __shared__ float red[8];
    float m = fmaxf(v0, v1);
    #pragma unroll
    for (int o = 16; o > 0; o >>= 1) m = fmaxf(m, __shfl_xor_sync(0xffffffffu, m, o));
    if ((tid & 31) == 0) red[tid >> 5] = m;
    __syncthreads();
    if (tid < 8) {
        float t = red[tid];
        #pragma unroll
        for (int o = 4; o > 0; o >>= 1) t = fmaxf(t, __shfl_xor_sync(0xffu, t, o));
        red[tid] = t;
    }
    __syncthreads();
    m = red[0];

    float e0 = expf(v0 - m), e1 = expf(v1 - m);

    __shared__ float red2[8];
    float s = e0 + e1;
    #pragma unroll
    for (int o = 16; o > 0; o >>= 1) s += __shfl_xor_sync(0xffffffffu, s, o);
    if ((tid & 31) == 0) red2[tid >> 5] = s;
    __syncthreads();
    if (tid < 8) {
        float t = red2[tid];
        #pragma unroll
        for (int o = 4; o > 0; o >>= 1) t += __shfl_xor_sync(0xffu, t, o);
        red2[tid] = t;
    }
    __syncthreads();
    s = red2[0];

    const float inv = 1.0f / s;
    __nv_bfloat16 h, l;
    __nv_bfloat16* dst = g_attn_p + row * (CH * 2);
    int d = tid;
    split2(e0 * inv, h, l);
    dst[(d >> 6) * 128 + (d & 63)]      = h;
    dst[(d >> 6) * 128 + 64 + (d & 63)] = l;
    d = tid + 256;
    split2(e1 * inv, h, l);
    dst[(d >> 6) * 128 + (d & 63)]      = h;
    dst[(d >> 6) * 128 + 64 + (d & 63)] = l;
}

// ---------------- kernel 4: out = attn @ v + x ----------------
// grid (NSP/128=32, CH/128=4, BATCH)
__global__ __launch_bounds__(256, 1) void out_gemm(
    const float* __restrict__ x, float* __restrict__ out)
{
    const int batch = blockIdx.z;
    const int c0 = blockIdx.y * 128, n0 = blockIdx.x * 128;

    const __nv_bfloat16* Ag = g_attn_p + ((size_t)batch * CH + c0) * (CH * 2);
    const __nv_bfloat16* Bg = g_vt + ((size_t)batch * NSP + n0) * (CH * 2);

    float acc[4][4][4];
    gemm_core<3>(Ag, Bg, CH / 64, CH * 2, CH * 2, acc);

    extern __shared__ char smem[];
    float* smemf = (float*)smem;
    const int tid = threadIdx.x, lane = tid & 31, w = tid >> 5;
    store_acc(smemf, acc, lane, (w >> 2) * 64, (w & 3) * 32, false);
    __syncthreads();

    #pragma unroll 4
    for (int rr = 0; rr < 16; rr++) {
        int row = w * 16 + rr;
        size_t off = ((size_t)batch * CH + c0 + row) * NSP + n0 + 4 * lane;
        float4 a = *(const float4*)(smemf + row * PITCH + 4 * lane);
        float4 xr = *(const float4*)(x + off);
        *(float4*)(out + off) = make_float4(a.x + xr.x, a.y + xr.y, a.z + xr.z, a.w + xr.w);
    }
}

// ---------------- split / pack kernels ----------------
__global__ __launch_bounds__(256) void split_w_kernel(
    const float* __restrict__ wq, const float* __restrict__ wk, const float* __restrict__ wv)
{
    int idx = blockIdx.x * 256 + threadIdx.x;          // 0 .. 3*512*512-1
    int which = idx >> 18;
    int rem = idx & 0x3FFFF;
    int row = rem >> 9, kk = rem & 511;
    const float* wsrc = (which == 0) ? wq : (which == 1) ? wk : wv;
    float f = wsrc[row * CH + kk];
    __nv_bfloat16 h, l; split2(f, h, l);
    __nv_bfloat16* dst = g_w + (size_t)which * CH * (CH * 2) + (size_t)row * (CH * 2)
                         + (kk >> 6) * 128 + (kk & 63);
    dst[0] = h; dst[64] = l;
}

// x[b][c][n] -> xt packed rows n, K=c
__global__ __launch_bounds__(256) void split_xt_kernel(const float* __restrict__ x)
{
    __shared__ float t[32][33];
    const int b = blockIdx.z;
    const int n0 = blockIdx.x * 32, c0 = blockIdx.y * 32;
    const int tx = threadIdx.x, ty = threadIdx.y;      // 32 x 8
    #pragma unroll
    for (int i = 0; i < 4; i++) {
        int c = c0 + ty + i * 8;
        t[ty + i * 8][tx] = x[((size_t)b * CH + c) * NSP + n0 + tx];
    }
    __syncthreads();
    #pragma unroll
    for (int i = 0; i < 4; i++) {
        int nl = ty + i * 8;
        float f = t[tx][nl];
        __nv_bfloat16 h, l; split2(f, h, l);
        int c = c0 + tx;
        __nv_bfloat16* dst = g_xt + ((size_t)b * NSP + n0 + nl) * (CH * 2)
                             + (c >> 6) * 128 + (c & 63);
        dst[0] = h; dst[64] = l;
    }
}

// ---------------- launch ----------------
extern "C" void kernel_launch(void* const* d_in, const int* in_sizes, int n_in,
                              void* d_out, int out_size) {
    const float* x  = (const float*)d_in[0];
    const float* wq = (const float*)d_in[1];
    const float* bq = (const float*)d_in[2];
    const float* wk = (const float*)d_in[3];
    const float* bk = (const float*)d_in[4];
    const float* wv = (const float*)d_in[5];
    const float* bv = (const float*)d_in[6];
    float* out = (float*)d_out;

    const int SMEM = 196608;   // 3 stages x 64KB
    cudaFuncSetAttribute(qkv_gemm,  cudaFuncAttributeMaxDynamicSharedMemorySize, SMEM);
    cudaFuncSetAttribute(attn_gemm, cudaFuncAttributeMaxDynamicSharedMemorySize, SMEM);
    cudaFuncSetAttribute(out_gemm,  cudaFuncAttributeMaxDynamicSharedMemorySize, SMEM);

    split_w_kernel<<<3 * CH * CH / 256, 256>>>(wq, wk, wv);
    split_xt_kernel<<<dim3(NSP / 32, CH / 32, BATCH), dim3(32, 8)>>>(x);

    qkv_gemm<<<dim3(NSP / 128, CH / 128, BATCH * 3), 256, SMEM>>>(bq, bk, bv);

    attn_gemm<<<dim3(CH / 128, CH / 128, BATCH), 256, SMEM>>>();

    softmax_kernel<<<BATCH * CH, 256>>>();

    out_gemm<<<dim3(NSP / 128, CH / 128, BATCH), 256, SMEM>>>(x, out);
}